// round 6
// baseline (speedup 1.0000x reference)
#include <cuda_runtime.h>
#include <cstdint>
#include <math.h>

#define T_    512
#define H_    1024
#define HD_   64
#define NQ_   16
#define NKV_  4
#define G_    4
#define E_    8
#define FFN_  1024
#define B_    4
#define Q_    128
#define P_    8
#define PS_   128
#define S_    1024
#define SW_   128
#define QKVD  1536
#define SCALE_ 0.125f
#define ALPHA_ 1.702f
#define LIMIT_ 7.0f
#define EPS_   1e-5f
#define NAPAD 2048

// ---------------- scratch ----------------
__device__ float g_x[T_ * H_];
__device__ float g_qkv[T_ * QKVD];
__device__ float g_attn[T_ * NQ_ * HD_];
__device__ float g_x2[T_ * H_];
__device__ int   g_eidx[T_ * 2];
__device__ float g_ewt[T_ * 2];
__device__ int   g_eoff[E_];
__device__ int   g_ecnt[E_];
__device__ int   g_tokof[NAPAD];
__device__ int   g_slotmap[T_ * 2];
__device__ float g_xg[NAPAD * H_];
__device__ float g_act[NAPAD * FFN_];
__device__ float g_eo[NAPAD * H_];

// ---------------- rmsnorm ----------------
__global__ void rmsnorm_kernel(const float* __restrict__ in,
                               const float* __restrict__ w,
                               float* __restrict__ out) {
    int t = blockIdx.x;
    const float* x = in + (size_t)t * H_;
    __shared__ float red[256];
    float ss = 0.f;
    for (int i = threadIdx.x; i < H_; i += 256) { float v = x[i]; ss += v * v; }
    red[threadIdx.x] = ss; __syncthreads();
    for (int s = 128; s > 0; s >>= 1) {
        if (threadIdx.x < s) red[threadIdx.x] += red[threadIdx.x + s];
        __syncthreads();
    }
    float r = rsqrtf(red[0] / (float)H_ + EPS_);
    for (int i = threadIdx.x; i < H_; i += 256)
        out[(size_t)t * H_ + i] = x[i] * w[i] * r;
}

// ---------------- mma / cp.async helpers ----------------
__device__ __forceinline__ uint32_t f2tf(uint32_t bits) {
    uint32_t r;
    asm("cvt.rna.tf32.f32 %0, %1;" : "=r"(r) : "f"(__uint_as_float(bits)));
    return r;
}
__device__ __forceinline__ void mma8(float* c, uint32_t a0, uint32_t a1,
                                     uint32_t a2, uint32_t a3,
                                     uint32_t b0, uint32_t b1) {
    asm volatile("mma.sync.aligned.m16n8k8.row.col.f32.tf32.tf32.f32 "
        "{%0,%1,%2,%3}, {%4,%5,%6,%7}, {%8,%9}, {%0,%1,%2,%3};"
        : "+f"(c[0]), "+f"(c[1]), "+f"(c[2]), "+f"(c[3])
        : "r"(a0), "r"(a1), "r"(a2), "r"(a3), "r"(b0), "r"(b1));
}
__device__ __forceinline__ void cp16(uint32_t dst, const void* src) {
    asm volatile("cp.async.cg.shared.global [%0], [%1], 16;" :: "r"(dst), "l"(src));
}
#define CP_COMMIT() asm volatile("cp.async.commit_group;")
#define CP_WAIT(n)  asm volatile("cp.async.wait_group %0;" :: "n"(n))

// ---------------- unified tf32 tensor-core GEMM, cp.async 2-stage ----------------
// MODE 0: +bias (qkv)  1: +bias+res (o-proj)  2: swiglu->act (gate_up)  3: +bias (down)
// Tile 128x128xBK16, 256 threads, warps 2(m) x 4(n), 64x32 per warp.
#define ALD 20   // As row stride (words)
#define BLD 136  // Bs row stride (words)
template<int MODE>
__global__ __launch_bounds__(256, 2) void gemm_tf32(
    const float* __restrict__ A, const float* __restrict__ Bw,
    const float* __restrict__ bias, const float* __restrict__ res,
    float* __restrict__ C, int K, int N,
    const int* __restrict__ eoff, const int* __restrict__ ecnt) {
    __shared__ uint32_t As[2][128][ALD];
    __shared__ uint32_t Bs[2][16][BLD];
    int tid = threadIdx.x, lane = tid & 31, wid = tid >> 5;
    int n0 = blockIdx.x * 128;
    int m0;
    if (MODE >= 2) {
        int e = blockIdx.z;
        if ((int)blockIdx.y * 128 >= ecnt[e]) return;
        m0 = eoff[e] + blockIdx.y * 128;
        Bw += (size_t)e * K * N;
        bias += (size_t)e * N;
    } else {
        m0 = blockIdx.y * 128;
    }
    int wm = (wid >> 2) * 64, wn = (wid & 3) * 32;

    uint32_t a_base = (uint32_t)__cvta_generic_to_shared(&As[0][0][0]);
    uint32_t b_base = (uint32_t)__cvta_generic_to_shared(&Bs[0][0][0]);
    int arow0 = tid >> 1, ac0 = (tid & 1) * 2;
    int brow0 = tid >> 4, bc0 = tid & 15;

    float acc[16][4];
    #pragma unroll
    for (int i = 0; i < 16; i++)
        #pragma unroll
        for (int j = 0; j < 4; j++) acc[i][j] = 0.f;

    int nchunks = K / 16;
    auto issue = [&](int c, int s) {
        int k0 = c * 16;
        #pragma unroll
        for (int l = 0; l < 2; l++) {
            int c4 = ac0 + l;
            cp16(a_base + (((s * 128 + arow0) * ALD) + c4 * 4) * 4,
                 &A[(size_t)(m0 + arow0) * K + k0 + c4 * 4]);
        }
        #pragma unroll
        for (int l = 0; l < 2; l++) {
            int cc = bc0 * 2 + l;
            cp16(b_base + (((s * 16 + brow0) * BLD) + cc * 4) * 4,
                 &Bw[(size_t)(k0 + brow0) * N + n0 + cc * 4]);
        }
        CP_COMMIT();
    };

    issue(0, 0);
    for (int c = 0; c < nchunks; c++) {
        int s = c & 1;
        if (c + 1 < nchunks) {
            issue(c + 1, (c + 1) & 1);
            CP_WAIT(1);
        } else {
            CP_WAIT(0);
        }
        __syncthreads();
        #pragma unroll
        for (int ks = 0; ks < 2; ks++) {
            int kq = ks * 8 + (lane & 3);
            uint32_t b[4][2];
            #pragma unroll
            for (int ni = 0; ni < 4; ni++) {
                int n = wn + ni * 8 + (lane >> 2);
                b[ni][0] = f2tf(Bs[s][kq][n]);
                b[ni][1] = f2tf(Bs[s][kq + 4][n]);
            }
            #pragma unroll
            for (int mi = 0; mi < 4; mi++) {
                int m = wm + mi * 16 + (lane >> 2);
                uint32_t a0 = f2tf(As[s][m][kq]);
                uint32_t a1 = f2tf(As[s][m + 8][kq]);
                uint32_t a2 = f2tf(As[s][m][kq + 4]);
                uint32_t a3 = f2tf(As[s][m + 8][kq + 4]);
                #pragma unroll
                for (int ni = 0; ni < 4; ni++)
                    mma8(acc[mi * 4 + ni], a0, a1, a2, a3, b[ni][0], b[ni][1]);
            }
        }
        __syncthreads();
    }
    // epilogue
    #pragma unroll
    for (int mi = 0; mi < 4; mi++) {
        #pragma unroll
        for (int ni = 0; ni < 4; ni++) {
            float* cc = acc[mi * 4 + ni];
            int row = m0 + wm + mi * 16 + (lane >> 2);
            int col = n0 + wn + ni * 8 + 2 * (lane & 3);
            #pragma unroll
            for (int h = 0; h < 2; h++) {
                int r = row + h * 8;
                float v0 = cc[h * 2 + 0] + bias[col];
                float v1 = cc[h * 2 + 1] + bias[col + 1];
                if (MODE == 2) {
                    float g = fminf(v0, LIMIT_);
                    float u = fminf(fmaxf(v1, -LIMIT_), LIMIT_);
                    float glu = g / (1.f + expf(-g * ALPHA_));
                    C[(size_t)r * (N >> 1) + (col >> 1)] = (u + 1.f) * glu;
                } else {
                    if (MODE == 1) {
                        v0 += res[(size_t)r * N + col];
                        v1 += res[(size_t)r * N + col + 1];
                    }
                    *(float2*)&C[(size_t)r * N + col] = make_float2(v0, v1);
                }
            }
        }
    }
}

// ---------------- sliding-window attention with sink ----------------
__global__ void attn_kernel(const float* __restrict__ qkv,
                            const float* __restrict__ kvc,
                            const int* __restrict__ pidx,
                            const float* __restrict__ mask,
                            const float* __restrict__ sinks,
                            float* __restrict__ attn) {
    int h = blockIdx.x, q = blockIdx.y, b = blockIdx.z;
    int t = b * Q_ + q;
    int qpos = S_ - Q_ + q;
    int kv = h / G_;
    int tid = threadIdx.x;

    __shared__ float qs[HD_];
    __shared__ float sc[SW_];
    __shared__ float red[SW_];
    __shared__ float vr[2][HD_];

    if (tid < HD_) qs[tid] = qkv[(size_t)t * QKVD + h * HD_ + tid] * SCALE_;
    __syncthreads();

    int kpos = qpos - (SW_ - 1) + tid;
    const float* kp;
    if (kpos < S_ - Q_) {
        int page = pidx[b * P_ + kpos / PS_];
        kp = kvc + ((((size_t)page * 2 + 0) * PS_ + (kpos % PS_)) * NKV_ + kv) * HD_;
    } else {
        kp = qkv + (size_t)(b * Q_ + kpos - (S_ - Q_)) * QKVD + NQ_ * HD_ + kv * HD_;
    }
    float s = 0.f;
    #pragma unroll
    for (int d = 0; d < HD_; d++) s += qs[d] * kp[d];
    s += mask[((size_t)b * Q_ + q) * S_ + kpos];
    sc[tid] = s;
    red[tid] = s;
    __syncthreads();
    for (int st = 64; st > 0; st >>= 1) {
        if (tid < st) red[tid] = fmaxf(red[tid], red[tid + st]);
        __syncthreads();
    }
    float m = red[0];
    __syncthreads();
    float p = expf(s - m);
    sc[tid] = p;
    red[tid] = p;
    __syncthreads();
    for (int st = 64; st > 0; st >>= 1) {
        if (tid < st) red[tid] += red[tid + st];
        __syncthreads();
    }
    float denom = red[0] + expf(sinks[h] - m);

    int half = tid >> 6;
    int d = tid & 63;
    float acc = 0.f;
    for (int jj = half * 64; jj < half * 64 + 64; jj++) {
        int kp2 = qpos - (SW_ - 1) + jj;
        const float* vp;
        if (kp2 < S_ - Q_) {
            int page = pidx[b * P_ + kp2 / PS_];
            vp = kvc + ((((size_t)page * 2 + 1) * PS_ + (kp2 % PS_)) * NKV_ + kv) * HD_;
        } else {
            vp = qkv + (size_t)(b * Q_ + kp2 - (S_ - Q_)) * QKVD + (NQ_ + NKV_) * HD_ + kv * HD_;
        }
        acc += sc[jj] * vp[d];
    }
    vr[half][d] = acc;
    __syncthreads();
    if (tid < HD_)
        attn[(size_t)t * (NQ_ * HD_) + h * HD_ + tid] = (vr[0][tid] + vr[1][tid]) / denom;
}

// ---------------- router ----------------
__global__ void router_kernel(const float* __restrict__ x2,
                              const float* __restrict__ wr,
                              const float* __restrict__ br,
                              int* __restrict__ eidx, float* __restrict__ ewt) {
    int t = blockIdx.x;
    int lane = threadIdx.x;
    float acc[E_] = {};
    for (int h = lane; h < H_; h += 32) {
        float xv = x2[(size_t)t * H_ + h];
        #pragma unroll
        for (int e = 0; e < E_; e++) acc[e] += xv * wr[h * E_ + e];
    }
    #pragma unroll
    for (int e = 0; e < E_; e++) {
        #pragma unroll
        for (int o = 16; o > 0; o >>= 1)
            acc[e] += __shfl_xor_sync(0xffffffffu, acc[e], o);
    }
    if (lane == 0) {
        float l[E_];
        #pragma unroll
        for (int e = 0; e < E_; e++) l[e] = acc[e] + br[e];
        int i0 = 0; float v0 = l[0];
        #pragma unroll
        for (int e = 1; e < E_; e++) if (l[e] > v0) { v0 = l[e]; i0 = e; }
        int i1 = -1; float v1 = -1e30f;
        #pragma unroll
        for (int e = 0; e < E_; e++)
            if (e != i0 && l[e] > v1) { v1 = l[e]; i1 = e; }
        float e1 = expf(v1 - v0);
        float inv = 1.f / (1.f + e1);
        eidx[t * 2 + 0] = i0; eidx[t * 2 + 1] = i1;
        ewt[t * 2 + 0] = inv; ewt[t * 2 + 1] = e1 * inv;
    }
}

// ---------------- route sort ----------------
__global__ void route_sort_kernel(const int* __restrict__ eidx,
                                  int* __restrict__ eoff, int* __restrict__ ecnt,
                                  int* __restrict__ tokof, int* __restrict__ slotmap) {
    __shared__ int cnt[E_];
    __shared__ int pos[E_];
    int tid = threadIdx.x;
    if (tid < E_) cnt[tid] = 0;
    for (int i = tid; i < NAPAD; i += 256) tokof[i] = -1;
    __syncthreads();
    for (int a = tid; a < T_ * 2; a += 256) atomicAdd(&cnt[eidx[a]], 1);
    __syncthreads();
    if (tid == 0) {
        int off = 0;
        for (int e = 0; e < E_; e++) {
            eoff[e] = off; ecnt[e] = cnt[e]; pos[e] = off;
            off += ((cnt[e] + 127) / 128) * 128;
        }
    }
    __syncthreads();
    for (int a = tid; a < T_ * 2; a += 256) {
        int e = eidx[a];
        int slot = atomicAdd(&pos[e], 1);
        tokof[slot] = a;
        slotmap[a] = slot;
    }
}

// ---------------- gather ----------------
__global__ void gather_kernel(const float* __restrict__ x2,
                              const int* __restrict__ tokof,
                              float* __restrict__ xg) {
    int slot = blockIdx.x;
    int a = tokof[slot];
    float4* dst = (float4*)(xg + (size_t)slot * H_);
    if (a < 0) {
        dst[threadIdx.x] = make_float4(0.f, 0.f, 0.f, 0.f);
    } else {
        const float4* src = (const float4*)(x2 + (size_t)(a >> 1) * H_);
        dst[threadIdx.x] = src[threadIdx.x];
    }
}

// ---------------- combine ----------------
__global__ void combine_kernel(const float* __restrict__ eo,
                               const int* __restrict__ slotmap,
                               const float* __restrict__ ewt,
                               float* __restrict__ out) {
    int t = blockIdx.x;
    int s0 = slotmap[t * 2 + 0], s1 = slotmap[t * 2 + 1];
    float w0 = ewt[t * 2 + 0], w1 = ewt[t * 2 + 1];
    const float4* e0 = (const float4*)(eo + (size_t)s0 * H_);
    const float4* e1 = (const float4*)(eo + (size_t)s1 * H_);
    float4* o = (float4*)(out + (size_t)t * H_);
    int i = threadIdx.x;
    float4 a = e0[i], b = e1[i], c = o[i];
    c.x += w0 * a.x + w1 * b.x;
    c.y += w0 * a.y + w1 * b.y;
    c.z += w0 * a.z + w1 * b.z;
    c.w += w0 * a.w + w1 * b.w;
    o[i] = c;
}

// ---------------- launch ----------------
extern "C" void kernel_launch(void* const* d_in, const int* in_sizes, int n_in,
                              void* d_out, int out_size) {
    const float* hidden = (const float*)d_in[0];
    const float* kvc    = (const float*)d_in[1];
    const float* mask   = (const float*)d_in[2];
    const int*   pidx   = (const int*)d_in[3];
    const float* sinks  = (const float*)d_in[4];
    const float* w_qkv  = (const float*)d_in[5];
    const float* b_qkv  = (const float*)d_in[6];
    const float* w_o    = (const float*)d_in[7];
    const float* b_o    = (const float*)d_in[8];
    const float* ln1    = (const float*)d_in[9];
    const float* ln2    = (const float*)d_in[10];
    const float* w_r    = (const float*)d_in[11];
    const float* b_r    = (const float*)d_in[12];
    const float* w_gu   = (const float*)d_in[13];
    const float* b_gu   = (const float*)d_in[14];
    const float* w_d    = (const float*)d_in[15];
    const float* b_d    = (const float*)d_in[16];
    float* out = (float*)d_out;

    float *px, *pqkv, *pattn, *px2, *pewt, *pxg, *pact, *peo;
    int *peidx, *peoff, *pecnt, *ptokof, *pslot;
    cudaGetSymbolAddress((void**)&px,     g_x);
    cudaGetSymbolAddress((void**)&pqkv,   g_qkv);
    cudaGetSymbolAddress((void**)&pattn,  g_attn);
    cudaGetSymbolAddress((void**)&px2,    g_x2);
    cudaGetSymbolAddress((void**)&peidx,  g_eidx);
    cudaGetSymbolAddress((void**)&pewt,   g_ewt);
    cudaGetSymbolAddress((void**)&peoff,  g_eoff);
    cudaGetSymbolAddress((void**)&pecnt,  g_ecnt);
    cudaGetSymbolAddress((void**)&ptokof, g_tokof);
    cudaGetSymbolAddress((void**)&pslot,  g_slotmap);
    cudaGetSymbolAddress((void**)&pxg,    g_xg);
    cudaGetSymbolAddress((void**)&pact,   g_act);
    cudaGetSymbolAddress((void**)&peo,    g_eo);

    rmsnorm_kernel<<<T_, 256>>>(hidden, ln1, px);
    gemm_tf32<0><<<dim3(QKVD / 128, T_ / 128), 256>>>(px, w_qkv, b_qkv, nullptr,
                                                      pqkv, H_, QKVD, nullptr, nullptr);
    attn_kernel<<<dim3(NQ_, Q_, B_), 128>>>(pqkv, kvc, pidx, mask, sinks, pattn);
    gemm_tf32<1><<<dim3(H_ / 128, T_ / 128), 256>>>(pattn, w_o, b_o, hidden,
                                                    out, H_, H_, nullptr, nullptr);
    rmsnorm_kernel<<<T_, 256>>>(out, ln2, px2);
    router_kernel<<<T_, 32>>>(px2, w_r, b_r, peidx, pewt);
    route_sort_kernel<<<1, 256>>>(peidx, peoff, pecnt, ptokof, pslot);
    gather_kernel<<<NAPAD, 256>>>(px2, ptokof, pxg);
    gemm_tf32<2><<<dim3(2 * FFN_ / 128, 8, E_), 256>>>(pxg, w_gu, b_gu, nullptr,
                                                       pact, H_, 2 * FFN_, peoff, pecnt);
    gemm_tf32<3><<<dim3(H_ / 128, 8, E_), 256>>>(pact, w_d, b_d, nullptr,
                                                 peo, FFN_, H_, peoff, pecnt);
    combine_kernel<<<T_, 256>>>(peo, pslot, pewt, out);
}

// round 7
// speedup vs baseline: 2.5335x; 2.5335x over previous
#include <cuda_runtime.h>
#include <cstdint>
#include <math.h>

#define T_    512
#define H_    1024
#define HD_   64
#define NQ_   16
#define NKV_  4
#define G_    4
#define E_    8
#define FFN_  1024
#define B_    4
#define Q_    128
#define P_    8
#define PS_   128
#define S_    1024
#define SW_   128
#define QKVD  1536
#define SCALE_ 0.125f
#define ALPHA_ 1.702f
#define LIMIT_ 7.0f
#define EPS_   1e-5f
#define NAPAD 2048

// ---------------- scratch ----------------
__device__ float g_x[T_ * H_];
__device__ float g_qkvp[2 * T_ * QKVD];
__device__ float g_qkv[T_ * QKVD];
__device__ float g_attn[T_ * NQ_ * HD_];
__device__ float g_outp[4 * T_ * H_];
__device__ float g_x2[T_ * H_];
__device__ int   g_eidx[T_ * 2];
__device__ float g_ewt[T_ * 2];
__device__ int   g_eoff[E_];
__device__ int   g_ecnt[E_];
__device__ int   g_tokof[NAPAD];
__device__ int   g_slotmap[T_ * 2];
__device__ float g_xg[NAPAD * H_];
__device__ float g_act[NAPAD * FFN_];
__device__ float g_eop[2 * NAPAD * H_];

// ---------------- helpers ----------------
__device__ __forceinline__ uint32_t f2tf_bits(uint32_t bits) {
    uint32_t r;
    asm("cvt.rna.tf32.f32 %0, %1;" : "=r"(r) : "f"(__uint_as_float(bits)));
    return r;
}
__device__ __forceinline__ float roundtf(float f) {
    uint32_t r;
    asm("cvt.rna.tf32.f32 %0, %1;" : "=r"(r) : "f"(f));
    return __uint_as_float(r);
}
__device__ __forceinline__ void mma8(float* c, uint32_t a0, uint32_t a1,
                                     uint32_t a2, uint32_t a3,
                                     uint32_t b0, uint32_t b1) {
    asm volatile("mma.sync.aligned.m16n8k8.row.col.f32.tf32.tf32.f32 "
        "{%0,%1,%2,%3}, {%4,%5,%6,%7}, {%8,%9}, {%0,%1,%2,%3};"
        : "+f"(c[0]), "+f"(c[1]), "+f"(c[2]), "+f"(c[3])
        : "r"(a0), "r"(a1), "r"(a2), "r"(a3), "r"(b0), "r"(b1));
}
__device__ __forceinline__ void cp16(uint32_t dst, const void* src) {
    asm volatile("cp.async.cg.shared.global [%0], [%1], 16;" :: "r"(dst), "l"(src));
}
#define CP_COMMIT() asm volatile("cp.async.commit_group;")
#define CP_WAIT(n)  asm volatile("cp.async.wait_group %0;" :: "n"(n))

// ---------------- rmsnorm ----------------
template<bool RND>
__global__ void rmsnorm_kernel(const float* __restrict__ in,
                               const float* __restrict__ w,
                               float* __restrict__ out) {
    int t = blockIdx.x;
    const float* x = in + (size_t)t * H_;
    __shared__ float red[256];
    float ss = 0.f;
    for (int i = threadIdx.x; i < H_; i += 256) { float v = x[i]; ss += v * v; }
    red[threadIdx.x] = ss; __syncthreads();
    for (int s = 128; s > 0; s >>= 1) {
        if (threadIdx.x < s) red[threadIdx.x] += red[threadIdx.x + s];
        __syncthreads();
    }
    float r = rsqrtf(red[0] / (float)H_ + EPS_);
    for (int i = threadIdx.x; i < H_; i += 256) {
        float v = x[i] * w[i] * r;
        out[(size_t)t * H_ + i] = RND ? roundtf(v) : v;
    }
}

// ---------------- unified tf32 GEMM, cp.async 2-stage, split-K ----------------
// MODE 0: raw partial (qkv / o-proj)    grid (N/128, M/128, SPLIT)
// MODE 2: +bias, swiglu, round -> act   grid (N/128, 8, E)
// MODE 3: raw partial, expert-tiled     grid (N/128, 8, E*SPLIT)
// A must already be tf32-rounded. B converted in-loop.
#define ALD 20
#define BLD 136
template<int MODE, int SPLIT>
__global__ __launch_bounds__(256, 2) void gemm_tf32(
    const float* __restrict__ A, const float* __restrict__ Bw,
    const float* __restrict__ bias,
    float* __restrict__ C, int K, int N, int partStride,
    const int* __restrict__ eoff, const int* __restrict__ ecnt) {
    __shared__ uint32_t As[2][128][ALD];
    __shared__ uint32_t Bs[2][16][BLD];
    int tid = threadIdx.x, lane = tid & 31, wid = tid >> 5;
    int n0 = blockIdx.x * 128;
    int m0, split;
    if (MODE >= 2) {
        int e = blockIdx.z / SPLIT;
        split = blockIdx.z % SPLIT;
        if ((int)blockIdx.y * 128 >= ecnt[e]) return;
        m0 = eoff[e] + blockIdx.y * 128;
        Bw += (size_t)e * K * N;
        if (MODE == 2) bias += (size_t)e * N;
    } else {
        split = blockIdx.z;
        m0 = blockIdx.y * 128;
    }
    int Ksub = K / SPLIT;
    int kbase = split * Ksub;
    C += (size_t)split * partStride;
    int wm = (wid >> 2) * 64, wn = (wid & 3) * 32;

    uint32_t a_base = (uint32_t)__cvta_generic_to_shared(&As[0][0][0]);
    uint32_t b_base = (uint32_t)__cvta_generic_to_shared(&Bs[0][0][0]);
    int arow0 = tid >> 1, ac0 = (tid & 1) * 2;
    int brow0 = tid >> 4, bc0 = tid & 15;

    float acc[16][4];
    #pragma unroll
    for (int i = 0; i < 16; i++)
        #pragma unroll
        for (int j = 0; j < 4; j++) acc[i][j] = 0.f;

    int nchunks = Ksub / 16;
    auto issue = [&](int c, int s) {
        int k0 = kbase + c * 16;
        #pragma unroll
        for (int l = 0; l < 2; l++) {
            int c4 = ac0 + l;
            cp16(a_base + (((s * 128 + arow0) * ALD) + c4 * 4) * 4,
                 &A[(size_t)(m0 + arow0) * K + k0 + c4 * 4]);
        }
        #pragma unroll
        for (int l = 0; l < 2; l++) {
            int cc = bc0 * 2 + l;
            cp16(b_base + (((s * 16 + brow0) * BLD) + cc * 4) * 4,
                 &Bw[(size_t)(k0 + brow0) * N + n0 + cc * 4]);
        }
        CP_COMMIT();
    };

    issue(0, 0);
    for (int c = 0; c < nchunks; c++) {
        int s = c & 1;
        if (c + 1 < nchunks) {
            issue(c + 1, (c + 1) & 1);
            CP_WAIT(1);
        } else {
            CP_WAIT(0);
        }
        __syncthreads();
        #pragma unroll
        for (int ks = 0; ks < 2; ks++) {
            int kq = ks * 8 + (lane & 3);
            uint32_t b[4][2];
            #pragma unroll
            for (int ni = 0; ni < 4; ni++) {
                int n = wn + ni * 8 + (lane >> 2);
                b[ni][0] = f2tf_bits(Bs[s][kq][n]);
                b[ni][1] = f2tf_bits(Bs[s][kq + 4][n]);
            }
            #pragma unroll
            for (int mi = 0; mi < 4; mi++) {
                int m = wm + mi * 16 + (lane >> 2);
                uint32_t a0 = As[s][m][kq];
                uint32_t a1 = As[s][m + 8][kq];
                uint32_t a2 = As[s][m][kq + 4];
                uint32_t a3 = As[s][m + 8][kq + 4];
                #pragma unroll
                for (int ni = 0; ni < 4; ni++)
                    mma8(acc[mi * 4 + ni], a0, a1, a2, a3, b[ni][0], b[ni][1]);
            }
        }
        __syncthreads();
    }
    #pragma unroll
    for (int mi = 0; mi < 4; mi++) {
        #pragma unroll
        for (int ni = 0; ni < 4; ni++) {
            float* cc = acc[mi * 4 + ni];
            int row = m0 + wm + mi * 16 + (lane >> 2);
            int col = n0 + wn + ni * 8 + 2 * (lane & 3);
            #pragma unroll
            for (int h = 0; h < 2; h++) {
                int r = row + h * 8;
                float v0 = cc[h * 2 + 0];
                float v1 = cc[h * 2 + 1];
                if (MODE == 2) {
                    float g = fminf(v0 + bias[col], LIMIT_);
                    float u = fminf(fmaxf(v1 + bias[col + 1], -LIMIT_), LIMIT_);
                    float glu = g / (1.f + expf(-g * ALPHA_));
                    C[(size_t)r * (N >> 1) + (col >> 1)] = roundtf((u + 1.f) * glu);
                } else {
                    *(float2*)&C[(size_t)r * N + col] = make_float2(v0, v1);
                }
            }
        }
    }
}

// ---------------- split reduces ----------------
__global__ void qkv_reduce(const float* __restrict__ p,
                           const float* __restrict__ bias,
                           float* __restrict__ q) {
    int t = blockIdx.x, i = threadIdx.x;       // 384 threads, one float4 each
    const float4* p0 = (const float4*)(p + (size_t)t * QKVD);
    const float4* p1 = (const float4*)(p + (size_t)(T_ + t) * QKVD);
    const float4* bb = (const float4*)bias;
    float4 a = p0[i], b = p1[i], c = bb[i];
    float4 r = make_float4(a.x + b.x + c.x, a.y + b.y + c.y,
                           a.z + b.z + c.z, a.w + b.w + c.w);
    ((float4*)(q + (size_t)t * QKVD))[i] = r;
}
__global__ void out_reduce(const float* __restrict__ p,
                           const float* __restrict__ hidden,
                           const float* __restrict__ bias,
                           float* __restrict__ out) {
    int t = blockIdx.x, i = threadIdx.x;       // 256 threads, one float4 each
    const float4* hh = (const float4*)(hidden + (size_t)t * H_);
    const float4* bb = (const float4*)bias;
    float4 r = hh[i], c = bb[i];
    r.x += c.x; r.y += c.y; r.z += c.z; r.w += c.w;
    #pragma unroll
    for (int s = 0; s < 4; s++) {
        float4 a = ((const float4*)(p + (size_t)(s * T_ + t) * H_))[i];
        r.x += a.x; r.y += a.y; r.z += a.z; r.w += a.w;
    }
    ((float4*)(out + (size_t)t * H_))[i] = r;
}

// ---------------- tiled sliding-window attention ----------------
// grid (Q_/16, NKV_, B_), 256 threads. 16 q x 4 heads per block share the
// 143-key window in smem. All window keys are causal-valid (mask==0 there).
#define KW_  143
#define KWP  144
#define KLD  68
#define PSLD 148
#define ATT_SMEM ((KWP*KLD*2 + 64*64 + 64*PSLD + 64) * 4)
__global__ void attn_tiled(const float* __restrict__ qkv,
                           const float* __restrict__ kvc,
                           const int* __restrict__ pidx,
                           const float* __restrict__ sinks,
                           float* __restrict__ attn) {
    extern __shared__ float sm[];
    float* Ks = sm;                    // [KWP][KLD]
    float* Vs = Ks + KWP * KLD;        // [KWP][KLD]
    float* Qs = Vs + KWP * KLD;        // [64][64]  row = ql*4 + g
    float* Ps = Qs + 64 * 64;          // [64][PSLD]
    float* dinv = Ps + 64 * PSLD;      // [64]
    int qt = blockIdx.x, kv = blockIdx.y, b = blockIdx.z;
    int tid = threadIdx.x;
    int qpos0 = S_ - Q_ + qt * 16;
    int base = qpos0 - (SW_ - 1);

    // load Q (scaled)
    #pragma unroll
    for (int l = 0; l < 4; l++) {
        int f = tid + 256 * l;                 // 64 rows x 16 f4
        int r = f >> 4, d4 = f & 15;
        int ql = r >> 2, g = r & 3;
        int t = b * Q_ + qt * 16 + ql;
        float4 v = *(const float4*)&qkv[(size_t)t * QKVD + (kv * G_ + g) * HD_ + d4 * 4];
        v.x *= SCALE_; v.y *= SCALE_; v.z *= SCALE_; v.w *= SCALE_;
        *(float4*)&Qs[r * 64 + d4 * 4] = v;
    }
    // load K,V window
    for (int f = tid; f < KW_ * 16; f += 256) {
        int k = f >> 4, d4 = f & 15;
        int kpos = base + k;
        const float *kp, *vp;
        if (kpos < S_ - Q_) {
            int page = pidx[b * P_ + (kpos >> 7)];
            size_t o = (((size_t)page * 2) * PS_ + (kpos & 127)) * NKV_ + kv;
            kp = kvc + o * HD_;
            vp = kvc + (o + (size_t)PS_ * NKV_) * HD_;
        } else {
            int t = b * Q_ + kpos - (S_ - Q_);
            kp = qkv + (size_t)t * QKVD + NQ_ * HD_ + kv * HD_;
            vp = qkv + (size_t)t * QKVD + (NQ_ + NKV_) * HD_ + kv * HD_;
        }
        *(float4*)&Ks[k * KLD + d4 * 4] = *(const float4*)&kp[d4 * 4];
        *(float4*)&Vs[k * KLD + d4 * 4] = *(const float4*)&vp[d4 * 4];
    }
    if (tid < 16) {
        *(float4*)&Ks[143 * KLD + tid * 4] = make_float4(0, 0, 0, 0);
        *(float4*)&Vs[143 * KLD + tid * 4] = make_float4(0, 0, 0, 0);
    }
    __syncthreads();

    int tx = tid & 15, ty = tid >> 4;
    // scores: 4 rows x 9 keys per thread
    float sacc[4][9];
    #pragma unroll
    for (int i = 0; i < 4; i++)
        #pragma unroll
        for (int j = 0; j < 9; j++) sacc[i][j] = 0.f;
    for (int d4 = 0; d4 < 16; d4++) {
        float4 qv[4];
        #pragma unroll
        for (int rr = 0; rr < 4; rr++)
            qv[rr] = *(float4*)&Qs[(ty * 4 + rr) * 64 + d4 * 4];
        #pragma unroll
        for (int kk = 0; kk < 9; kk++) {
            int k = kk * 16 + tx;
            float4 kf = *(float4*)&Ks[k * KLD + d4 * 4];
            #pragma unroll
            for (int rr = 0; rr < 4; rr++)
                sacc[rr][kk] += qv[rr].x * kf.x + qv[rr].y * kf.y
                              + qv[rr].z * kf.z + qv[rr].w * kf.w;
        }
    }
    // softmax per row (window [ql, ql+127])
    #pragma unroll
    for (int rr = 0; rr < 4; rr++) {
        int r = ty * 4 + rr;
        int ql = r >> 2;
        float mx = -1e30f;
        #pragma unroll
        for (int kk = 0; kk < 9; kk++) {
            int k = kk * 16 + tx;
            if (k >= ql && k <= ql + 127) mx = fmaxf(mx, sacc[rr][kk]);
        }
        #pragma unroll
        for (int o = 1; o < 16; o <<= 1)
            mx = fmaxf(mx, __shfl_xor_sync(0xffffffffu, mx, o));
        float sum = 0.f;
        #pragma unroll
        for (int kk = 0; kk < 9; kk++) {
            int k = kk * 16 + tx;
            float pv = 0.f;
            if (k >= ql && k <= ql + 127) {
                pv = expf(sacc[rr][kk] - mx);
                sum += pv;
            }
            Ps[r * PSLD + k] = pv;
        }
        #pragma unroll
        for (int o = 1; o < 16; o <<= 1)
            sum += __shfl_xor_sync(0xffffffffu, sum, o);
        if (tx == 0)
            dinv[r] = 1.f / (sum + expf(sinks[kv * G_ + (r & 3)] - mx));
    }
    __syncthreads();
    // PV: 4 rows x 1 float4 (dims tx*4..)
    float4 oacc[4];
    #pragma unroll
    for (int rr = 0; rr < 4; rr++) oacc[rr] = make_float4(0, 0, 0, 0);
    for (int k = 0; k < KW_; k++) {
        float4 v = *(float4*)&Vs[k * KLD + tx * 4];
        #pragma unroll
        for (int rr = 0; rr < 4; rr++) {
            float p = Ps[(ty * 4 + rr) * PSLD + k];
            oacc[rr].x += p * v.x; oacc[rr].y += p * v.y;
            oacc[rr].z += p * v.z; oacc[rr].w += p * v.w;
        }
    }
    #pragma unroll
    for (int rr = 0; rr < 4; rr++) {
        int r = ty * 4 + rr;
        float di = dinv[r];
        int t = b * Q_ + qt * 16 + (r >> 2);
        int head = kv * G_ + (r & 3);
        float4 o;
        o.x = roundtf(oacc[rr].x * di);
        o.y = roundtf(oacc[rr].y * di);
        o.z = roundtf(oacc[rr].z * di);
        o.w = roundtf(oacc[rr].w * di);
        *(float4*)&attn[(size_t)t * (NQ_ * HD_) + head * HD_ + tx * 4] = o;
    }
}

// ---------------- router ----------------
__global__ void router_kernel(const float* __restrict__ x2,
                              const float* __restrict__ wr,
                              const float* __restrict__ br,
                              int* __restrict__ eidx, float* __restrict__ ewt) {
    int t = blockIdx.x;
    int lane = threadIdx.x;
    float acc[E_] = {};
    for (int h = lane; h < H_; h += 32) {
        float xv = x2[(size_t)t * H_ + h];
        #pragma unroll
        for (int e = 0; e < E_; e++) acc[e] += xv * wr[h * E_ + e];
    }
    #pragma unroll
    for (int e = 0; e < E_; e++) {
        #pragma unroll
        for (int o = 16; o > 0; o >>= 1)
            acc[e] += __shfl_xor_sync(0xffffffffu, acc[e], o);
    }
    if (lane == 0) {
        float l[E_];
        #pragma unroll
        for (int e = 0; e < E_; e++) l[e] = acc[e] + br[e];
        int i0 = 0; float v0 = l[0];
        #pragma unroll
        for (int e = 1; e < E_; e++) if (l[e] > v0) { v0 = l[e]; i0 = e; }
        int i1 = -1; float v1 = -1e30f;
        #pragma unroll
        for (int e = 0; e < E_; e++)
            if (e != i0 && l[e] > v1) { v1 = l[e]; i1 = e; }
        float e1 = expf(v1 - v0);
        float inv = 1.f / (1.f + e1);
        eidx[t * 2 + 0] = i0; eidx[t * 2 + 1] = i1;
        ewt[t * 2 + 0] = inv; ewt[t * 2 + 1] = e1 * inv;
    }
}

// ---------------- route sort ----------------
__global__ void route_sort_kernel(const int* __restrict__ eidx,
                                  int* __restrict__ eoff, int* __restrict__ ecnt,
                                  int* __restrict__ tokof, int* __restrict__ slotmap) {
    __shared__ int cnt[E_];
    __shared__ int pos[E_];
    int tid = threadIdx.x;
    if (tid < E_) cnt[tid] = 0;
    for (int i = tid; i < NAPAD; i += 256) tokof[i] = -1;
    __syncthreads();
    for (int a = tid; a < T_ * 2; a += 256) atomicAdd(&cnt[eidx[a]], 1);
    __syncthreads();
    if (tid == 0) {
        int off = 0;
        for (int e = 0; e < E_; e++) {
            eoff[e] = off; ecnt[e] = cnt[e]; pos[e] = off;
            off += ((cnt[e] + 127) / 128) * 128;
        }
    }
    __syncthreads();
    for (int a = tid; a < T_ * 2; a += 256) {
        int e = eidx[a];
        int slot = atomicAdd(&pos[e], 1);
        tokof[slot] = a;
        slotmap[a] = slot;
    }
}

// ---------------- gather (rounds to tf32 for GEMM A) ----------------
__global__ void gather_kernel(const float* __restrict__ x2,
                              const int* __restrict__ tokof,
                              float* __restrict__ xg) {
    int slot = blockIdx.x;
    int a = tokof[slot];
    float4* dst = (float4*)(xg + (size_t)slot * H_);
    if (a < 0) {
        dst[threadIdx.x] = make_float4(0.f, 0.f, 0.f, 0.f);
    } else {
        float4 v = ((const float4*)(x2 + (size_t)(a >> 1) * H_))[threadIdx.x];
        v.x = roundtf(v.x); v.y = roundtf(v.y);
        v.z = roundtf(v.z); v.w = roundtf(v.w);
        dst[threadIdx.x] = v;
    }
}

// ---------------- combine: out += Σ w*(eop0+eop1+bd) ----------------
__global__ void combine_kernel(const float* __restrict__ eop,
                               const int* __restrict__ slotmap,
                               const int* __restrict__ eidx,
                               const float* __restrict__ ewt,
                               const float* __restrict__ bd,
                               float* __restrict__ out) {
    int t = blockIdx.x, i = threadIdx.x;
    float4 o = ((float4*)(out + (size_t)t * H_))[i];
    #pragma unroll
    for (int ei = 0; ei < 2; ei++) {
        int s = slotmap[t * 2 + ei];
        int e = eidx[t * 2 + ei];
        float w = ewt[t * 2 + ei];
        float4 a = ((const float4*)(eop + (size_t)s * H_))[i];
        float4 b = ((const float4*)(eop + (size_t)(NAPAD + s) * H_))[i];
        float4 c = ((const float4*)(bd + (size_t)e * H_))[i];
        o.x += w * (a.x + b.x + c.x);
        o.y += w * (a.y + b.y + c.y);
        o.z += w * (a.z + b.z + c.z);
        o.w += w * (a.w + b.w + c.w);
    }
    ((float4*)(out + (size_t)t * H_))[i] = o;
}

// ---------------- launch ----------------
extern "C" void kernel_launch(void* const* d_in, const int* in_sizes, int n_in,
                              void* d_out, int out_size) {
    const float* hidden = (const float*)d_in[0];
    const float* kvc    = (const float*)d_in[1];
    const int*   pidx   = (const int*)d_in[3];
    const float* sinks  = (const float*)d_in[4];
    const float* w_qkv  = (const float*)d_in[5];
    const float* b_qkv  = (const float*)d_in[6];
    const float* w_o    = (const float*)d_in[7];
    const float* b_o    = (const float*)d_in[8];
    const float* ln1    = (const float*)d_in[9];
    const float* ln2    = (const float*)d_in[10];
    const float* w_r    = (const float*)d_in[11];
    const float* b_r    = (const float*)d_in[12];
    const float* w_gu   = (const float*)d_in[13];
    const float* b_gu   = (const float*)d_in[14];
    const float* w_d    = (const float*)d_in[15];
    const float* b_d    = (const float*)d_in[16];
    float* out = (float*)d_out;

    float *px, *pqkvp, *pqkv, *pattn, *poutp, *px2, *pewt, *pxg, *pact, *peop;
    int *peidx, *peoff, *pecnt, *ptokof, *pslot;
    cudaGetSymbolAddress((void**)&px,     g_x);
    cudaGetSymbolAddress((void**)&pqkvp,  g_qkvp);
    cudaGetSymbolAddress((void**)&pqkv,   g_qkv);
    cudaGetSymbolAddress((void**)&pattn,  g_attn);
    cudaGetSymbolAddress((void**)&poutp,  g_outp);
    cudaGetSymbolAddress((void**)&px2,    g_x2);
    cudaGetSymbolAddress((void**)&peidx,  g_eidx);
    cudaGetSymbolAddress((void**)&pewt,   g_ewt);
    cudaGetSymbolAddress((void**)&peoff,  g_eoff);
    cudaGetSymbolAddress((void**)&pecnt,  g_ecnt);
    cudaGetSymbolAddress((void**)&ptokof, g_tokof);
    cudaGetSymbolAddress((void**)&pslot,  g_slotmap);
    cudaGetSymbolAddress((void**)&pxg,    g_xg);
    cudaGetSymbolAddress((void**)&pact,   g_act);
    cudaGetSymbolAddress((void**)&peop,   g_eop);

    cudaFuncSetAttribute(attn_tiled,
                         cudaFuncAttributeMaxDynamicSharedMemorySize, ATT_SMEM);

    rmsnorm_kernel<true><<<T_, 256>>>(hidden, ln1, px);
    gemm_tf32<0, 2><<<dim3(QKVD / 128, T_ / 128, 2), 256>>>(
        px, w_qkv, nullptr, pqkvp, H_, QKVD, T_ * QKVD, nullptr, nullptr);
    qkv_reduce<<<T_, 384>>>(pqkvp, b_qkv, pqkv);
    attn_tiled<<<dim3(Q_ / 16, NKV_, B_), 256, ATT_SMEM>>>(
        pqkv, kvc, pidx, sinks, pattn);
    gemm_tf32<0, 4><<<dim3(H_ / 128, T_ / 128, 4), 256>>>(
        pattn, w_o, nullptr, poutp, H_, H_, T_ * H_, nullptr, nullptr);
    out_reduce<<<T_, 256>>>(poutp, hidden, b_o, out);
    rmsnorm_kernel<false><<<T_, 256>>>(out, ln2, px2);
    router_kernel<<<T_, 32>>>(px2, w_r, b_r, peidx, pewt);
    route_sort_kernel<<<1, 256>>>(peidx, peoff, pecnt, ptokof, pslot);
    gather_kernel<<<NAPAD, 256>>>(px2, ptokof, pxg);
    gemm_tf32<2, 1><<<dim3(2 * FFN_ / 128, 8, E_), 256>>>(
        pxg, w_gu, b_gu, pact, H_, 2 * FFN_, 0, peoff, pecnt);
    gemm_tf32<3, 2><<<dim3(H_ / 128, 8, E_ * 2), 256>>>(
        pact, w_d, nullptr, peop, FFN_, H_, NAPAD * H_, peoff, pecnt);
    combine_kernel<<<T_, 256>>>(peop, pslot, peidx, pewt, b_d, out);
}

// round 8
// speedup vs baseline: 2.5420x; 1.0034x over previous
#include <cuda_runtime.h>
#include <cstdint>
#include <math.h>

#define T_    512
#define H_    1024
#define HD_   64
#define NQ_   16
#define NKV_  4
#define G_    4
#define E_    8
#define FFN_  1024
#define B_    4
#define Q_    128
#define P_    8
#define PS_   128
#define S_    1024
#define SW_   128
#define QKVD  1536
#define SCALE_ 0.125f
#define ALPHA_ 1.702f
#define LIMIT_ 7.0f
#define EPS_   1e-5f
#define NAPAD 2048

// ---------------- scratch ----------------
__device__ float g_x[T_ * H_];
__device__ float g_qkvp[2 * T_ * QKVD];
__device__ float g_attn[T_ * NQ_ * HD_];
__device__ float g_outp[4 * T_ * H_];
__device__ float g_x2[T_ * H_];
__device__ int   g_eidx[T_ * 2];
__device__ float g_ewt[T_ * 2];
__device__ int   g_eoff[E_];
__device__ int   g_ecnt[E_];
__device__ int   g_tokof[NAPAD];
__device__ int   g_slotmap[T_ * 2];
__device__ float g_xg[NAPAD * H_];
__device__ float g_act[NAPAD * FFN_];
__device__ float g_eop[2 * NAPAD * H_];

// ---------------- helpers ----------------
__device__ __forceinline__ uint32_t f2tf_bits(uint32_t bits) {
    uint32_t r;
    asm("cvt.rna.tf32.f32 %0, %1;" : "=r"(r) : "f"(__uint_as_float(bits)));
    return r;
}
__device__ __forceinline__ float roundtf(float f) {
    uint32_t r;
    asm("cvt.rna.tf32.f32 %0, %1;" : "=r"(r) : "f"(f));
    return __uint_as_float(r);
}
__device__ __forceinline__ void mma8(float* c, uint32_t a0, uint32_t a1,
                                     uint32_t a2, uint32_t a3,
                                     uint32_t b0, uint32_t b1) {
    asm volatile("mma.sync.aligned.m16n8k8.row.col.f32.tf32.tf32.f32 "
        "{%0,%1,%2,%3}, {%4,%5,%6,%7}, {%8,%9}, {%0,%1,%2,%3};"
        : "+f"(c[0]), "+f"(c[1]), "+f"(c[2]), "+f"(c[3])
        : "r"(a0), "r"(a1), "r"(a2), "r"(a3), "r"(b0), "r"(b1));
}
__device__ __forceinline__ void cp16(uint32_t dst, const void* src) {
    asm volatile("cp.async.cg.shared.global [%0], [%1], 16;" :: "r"(dst), "l"(src));
}
#define CP_COMMIT() asm volatile("cp.async.commit_group;")
#define CP_WAIT(n)  asm volatile("cp.async.wait_group %0;" :: "n"(n))

// ---------------- rmsnorm (stage 1, rounds output for GEMM A) ----------------
__global__ void rmsnorm_kernel(const float* __restrict__ in,
                               const float* __restrict__ w,
                               float* __restrict__ out) {
    int t = blockIdx.x;
    const float* x = in + (size_t)t * H_;
    __shared__ float red[256];
    float ss = 0.f;
    for (int i = threadIdx.x; i < H_; i += 256) { float v = x[i]; ss += v * v; }
    red[threadIdx.x] = ss; __syncthreads();
    for (int s = 128; s > 0; s >>= 1) {
        if (threadIdx.x < s) red[threadIdx.x] += red[threadIdx.x + s];
        __syncthreads();
    }
    float r = rsqrtf(red[0] / (float)H_ + EPS_);
    for (int i = threadIdx.x; i < H_; i += 256)
        out[(size_t)t * H_ + i] = roundtf(x[i] * w[i] * r);
}

// ---------------- unified tf32 GEMM, 4-stage cp.async, split-K ----------------
// MODE 0: raw partial   MODE 2: +bias swiglu round -> act   MODE 3: raw partial expert
#define ALD 20
#define BLD 136
#define GSTG 4
#define GEMM_SMEM ((GSTG * 128 * ALD + GSTG * 16 * BLD) * 4)
template<int MODE, int SPLIT>
__global__ __launch_bounds__(256) void gemm_tf32(
    const float* __restrict__ A, const float* __restrict__ Bw,
    const float* __restrict__ bias,
    float* __restrict__ C, int K, int N, int partStride,
    const int* __restrict__ eoff, const int* __restrict__ ecnt) {
    extern __shared__ uint32_t gsm[];
    uint32_t* As = gsm;                         // [GSTG][128][ALD]
    uint32_t* Bs = gsm + GSTG * 128 * ALD;      // [GSTG][16][BLD]
    int tid = threadIdx.x, lane = tid & 31, wid = tid >> 5;
    int n0 = blockIdx.x * 128;
    int m0, split;
    if (MODE >= 2) {
        int e = blockIdx.z / SPLIT;
        split = blockIdx.z % SPLIT;
        if ((int)blockIdx.y * 128 >= ecnt[e]) return;
        m0 = eoff[e] + blockIdx.y * 128;
        Bw += (size_t)e * K * N;
        if (MODE == 2) bias += (size_t)e * N;
    } else {
        split = blockIdx.z;
        m0 = blockIdx.y * 128;
    }
    int Ksub = K / SPLIT;
    int kbase = split * Ksub;
    C += (size_t)split * partStride;
    int wm = (wid >> 2) * 64, wn = (wid & 3) * 32;

    uint32_t a_base = (uint32_t)__cvta_generic_to_shared(As);
    uint32_t b_base = (uint32_t)__cvta_generic_to_shared(Bs);
    int arow0 = tid >> 1, ac0 = (tid & 1) * 2;
    int brow0 = tid >> 4, bc0 = tid & 15;

    float acc[16][4];
    #pragma unroll
    for (int i = 0; i < 16; i++)
        #pragma unroll
        for (int j = 0; j < 4; j++) acc[i][j] = 0.f;

    int nchunks = Ksub / 16;
    auto issue = [&](int c, int s) {
        int k0 = kbase + c * 16;
        #pragma unroll
        for (int l = 0; l < 2; l++) {
            int c4 = ac0 + l;
            cp16(a_base + (((s * 128 + arow0) * ALD) + c4 * 4) * 4,
                 &A[(size_t)(m0 + arow0) * K + k0 + c4 * 4]);
        }
        #pragma unroll
        for (int l = 0; l < 2; l++) {
            int cc = bc0 * 2 + l;
            cp16(b_base + (((s * 16 + brow0) * BLD) + cc * 4) * 4,
                 &Bw[(size_t)(k0 + brow0) * N + n0 + cc * 4]);
        }
        CP_COMMIT();
    };

    issue(0, 0); issue(1, 1); issue(2, 2);
    for (int c = 0; c < nchunks; c++) {
        CP_WAIT(2);
        __syncthreads();
        if (c + 3 < nchunks) issue(c + 3, (c + 3) & 3); else CP_COMMIT();
        int s = c & 3;
        #pragma unroll
        for (int ks = 0; ks < 2; ks++) {
            int kq = ks * 8 + (lane & 3);
            uint32_t b[4][2];
            #pragma unroll
            for (int ni = 0; ni < 4; ni++) {
                int n = wn + ni * 8 + (lane >> 2);
                b[ni][0] = f2tf_bits(Bs[(s * 16 + kq) * BLD + n]);
                b[ni][1] = f2tf_bits(Bs[(s * 16 + kq + 4) * BLD + n]);
            }
            #pragma unroll
            for (int mi = 0; mi < 4; mi++) {
                int m = wm + mi * 16 + (lane >> 2);
                uint32_t a0 = As[(s * 128 + m) * ALD + kq];
                uint32_t a1 = As[(s * 128 + m + 8) * ALD + kq];
                uint32_t a2 = As[(s * 128 + m) * ALD + kq + 4];
                uint32_t a3 = As[(s * 128 + m + 8) * ALD + kq + 4];
                #pragma unroll
                for (int ni = 0; ni < 4; ni++)
                    mma8(acc[mi * 4 + ni], a0, a1, a2, a3, b[ni][0], b[ni][1]);
            }
        }
    }
    #pragma unroll
    for (int mi = 0; mi < 4; mi++) {
        #pragma unroll
        for (int ni = 0; ni < 4; ni++) {
            float* cc = acc[mi * 4 + ni];
            int row = m0 + wm + mi * 16 + (lane >> 2);
            int col = n0 + wn + ni * 8 + 2 * (lane & 3);
            #pragma unroll
            for (int h = 0; h < 2; h++) {
                int r = row + h * 8;
                float v0 = cc[h * 2 + 0];
                float v1 = cc[h * 2 + 1];
                if (MODE == 2) {
                    float g = fminf(v0 + bias[col], LIMIT_);
                    float u = fminf(fmaxf(v1 + bias[col + 1], -LIMIT_), LIMIT_);
                    float glu = g / (1.f + expf(-g * ALPHA_));
                    C[(size_t)r * (N >> 1) + (col >> 1)] = roundtf((u + 1.f) * glu);
                } else {
                    *(float2*)&C[(size_t)r * N + col] = make_float2(v0, v1);
                }
            }
        }
    }
}

// ---------------- out reduce (o-proj partials + residual + bias) ----------------
__global__ void out_reduce(const float* __restrict__ p,
                           const float* __restrict__ hidden,
                           const float* __restrict__ bias,
                           float* __restrict__ out) {
    int t = blockIdx.x, i = threadIdx.x;
    const float4* hh = (const float4*)(hidden + (size_t)t * H_);
    const float4* bb = (const float4*)bias;
    float4 r = hh[i], c = bb[i];
    r.x += c.x; r.y += c.y; r.z += c.z; r.w += c.w;
    #pragma unroll
    for (int s = 0; s < 4; s++) {
        float4 a = ((const float4*)(p + (size_t)(s * T_ + t) * H_))[i];
        r.x += a.x; r.y += a.y; r.z += a.z; r.w += a.w;
    }
    ((float4*)(out + (size_t)t * H_))[i] = r;
}

// ---------------- tensor-core sliding-window attention (fused qkv reduce) ----
// grid (Q_/16, NKV_, B_), 256 threads = 8 warps. 64 rows (16q x 4g) x 144 keys.
#define QLD 68
#define KVLD 72
#define PLD 148
#define ATT_SMEM ((64 * QLD + 2 * 144 * KVLD + 64 * PLD + 64) * 4)
__global__ void attn_mma(const float* __restrict__ qkvp,
                         const float* __restrict__ bqkv,
                         const float* __restrict__ kvc,
                         const int* __restrict__ pidx,
                         const float* __restrict__ sinks,
                         float* __restrict__ attn) {
    extern __shared__ float sm[];
    float* Qs = sm;                       // [64][QLD] rounded tf32 floats
    float* Ks = Qs + 64 * QLD;            // [144][KVLD]
    float* Vs = Ks + 144 * KVLD;          // [144][KVLD]
    float* Ps = Vs + 144 * KVLD;          // [64][PLD]
    float* dinv = Ps + 64 * PLD;          // [64]
    int qt = blockIdx.x, kv = blockIdx.y, b = blockIdx.z;
    int tid = threadIdx.x, lane = tid & 31, wid = tid >> 5;
    int qpos0 = S_ - Q_ + qt * 16;
    int base = qpos0 - (SW_ - 1);
    const float* p0 = qkvp;
    const float* p1 = qkvp + (size_t)T_ * QKVD;

    // Q: reduce partials + bias, scale, round
    #pragma unroll
    for (int l = 0; l < 4; l++) {
        int f = tid + 256 * l;            // 64 rows x 16 f4
        int r = f >> 4, d4 = f & 15;
        int ql = r >> 2, g = r & 3;
        size_t o = (size_t)(b * Q_ + qt * 16 + ql) * QKVD + (kv * G_ + g) * HD_ + d4 * 4;
        float4 a = *(const float4*)&p0[o];
        float4 c = *(const float4*)&p1[o];
        float4 bb = *(const float4*)&bqkv[(kv * G_ + g) * HD_ + d4 * 4];
        Qs[r * QLD + d4 * 4 + 0] = roundtf((a.x + c.x + bb.x) * SCALE_);
        Qs[r * QLD + d4 * 4 + 1] = roundtf((a.y + c.y + bb.y) * SCALE_);
        Qs[r * QLD + d4 * 4 + 2] = roundtf((a.z + c.z + bb.z) * SCALE_);
        Qs[r * QLD + d4 * 4 + 3] = roundtf((a.w + c.w + bb.w) * SCALE_);
    }
    // K, V window (old from cache; new from partials+bias)
    for (int f = tid; f < 143 * 16; f += 256) {
        int k = f >> 4, d4 = f & 15;
        int kpos = base + k;
        float4 kf, vf;
        if (kpos < S_ - Q_) {
            int page = pidx[b * P_ + (kpos >> 7)];
            size_t o = (((size_t)page * 2) * PS_ + (kpos & 127)) * NKV_ + kv;
            kf = *(const float4*)&kvc[o * HD_ + d4 * 4];
            vf = *(const float4*)&kvc[(o + (size_t)PS_ * NKV_) * HD_ + d4 * 4];
        } else {
            size_t t = (size_t)(b * Q_ + kpos - (S_ - Q_)) * QKVD;
            int ck = NQ_ * HD_ + kv * HD_ + d4 * 4;
            int cv = (NQ_ + NKV_) * HD_ + kv * HD_ + d4 * 4;
            float4 a0 = *(const float4*)&p0[t + ck];
            float4 a1 = *(const float4*)&p1[t + ck];
            float4 b0 = *(const float4*)&bqkv[ck];
            kf = make_float4(a0.x + a1.x + b0.x, a0.y + a1.y + b0.y,
                             a0.z + a1.z + b0.z, a0.w + a1.w + b0.w);
            float4 c0 = *(const float4*)&p0[t + cv];
            float4 c1 = *(const float4*)&p1[t + cv];
            float4 b1 = *(const float4*)&bqkv[cv];
            vf = make_float4(c0.x + c1.x + b1.x, c0.y + c1.y + b1.y,
                             c0.z + c1.z + b1.z, c0.w + c1.w + b1.w);
        }
        *(float4*)&Ks[k * KVLD + d4 * 4] = kf;
        *(float4*)&Vs[k * KVLD + d4 * 4] = vf;
    }
    if (tid < 32) {
        int d4 = tid & 15;
        if (tid < 16) *(float4*)&Ks[143 * KVLD + d4 * 4] = make_float4(0, 0, 0, 0);
        else          *(float4*)&Vs[143 * KVLD + d4 * 4] = make_float4(0, 0, 0, 0);
    }
    __syncthreads();

    // scores: 64 x 144 = (4 m-tiles)(18 n-tiles), warps 4m x 2n (9 n-tiles each)
    int mt = wid & 3, nh = wid >> 2;
    int r0 = mt * 16 + (lane >> 2);
    {
        float sacc[9][4];
        #pragma unroll
        for (int i = 0; i < 9; i++)
            #pragma unroll
            for (int j = 0; j < 4; j++) sacc[i][j] = 0.f;
        #pragma unroll
        for (int kk = 0; kk < 8; kk++) {
            int kq = kk * 8 + (lane & 3);
            uint32_t a0 = __float_as_uint(Qs[r0 * QLD + kq]);
            uint32_t a1 = __float_as_uint(Qs[(r0 + 8) * QLD + kq]);
            uint32_t a2 = __float_as_uint(Qs[r0 * QLD + kq + 4]);
            uint32_t a3 = __float_as_uint(Qs[(r0 + 8) * QLD + kq + 4]);
            #pragma unroll
            for (int ni = 0; ni < 9; ni++) {
                int n = nh * 72 + ni * 8 + (lane >> 2);
                uint32_t b0 = f2tf_bits(__float_as_uint(Ks[n * KVLD + kq]));
                uint32_t b1 = f2tf_bits(__float_as_uint(Ks[n * KVLD + kq + 4]));
                mma8(sacc[ni], a0, a1, a2, a3, b0, b1);
            }
        }
        // write scores with window mask
        #pragma unroll
        for (int ni = 0; ni < 9; ni++) {
            #pragma unroll
            for (int h = 0; h < 2; h++) {
                int row = r0 + h * 8;
                int ql = row >> 2;
                int cb = nh * 72 + ni * 8 + 2 * (lane & 3);
                float v0 = sacc[ni][h * 2 + 0];
                float v1 = sacc[ni][h * 2 + 1];
                if (cb < ql || cb > ql + 127) v0 = -1e30f;
                if (cb + 1 < ql || cb + 1 > ql + 127) v1 = -1e30f;
                Ps[row * PLD + cb] = v0;
                Ps[row * PLD + cb + 1] = v1;
            }
        }
    }
    __syncthreads();

    // softmax: 4 threads per row, 36 cols each
    {
        int row = tid >> 2, part = tid & 3;
        float mx = -1e30f;
        #pragma unroll 4
        for (int j = 0; j < 36; j++)
            mx = fmaxf(mx, Ps[row * PLD + part * 36 + j]);
        mx = fmaxf(mx, __shfl_xor_sync(0xffffffffu, mx, 1));
        mx = fmaxf(mx, __shfl_xor_sync(0xffffffffu, mx, 2));
        float sum = 0.f;
        #pragma unroll 4
        for (int j = 0; j < 36; j++) {
            float p = expf(Ps[row * PLD + part * 36 + j] - mx);
            float pr = roundtf(p);
            Ps[row * PLD + part * 36 + j] = pr;
            sum += p;
        }
        sum += __shfl_xor_sync(0xffffffffu, sum, 1);
        sum += __shfl_xor_sync(0xffffffffu, sum, 2);
        if (part == 0)
            dinv[row] = 1.f / (sum + expf(sinks[kv * G_ + (row & 3)] - mx));
    }
    __syncthreads();

    // PV: 64 x 64 over K=144, warps 4m x 2n (4 n-tiles each)
    {
        float oacc[4][4];
        #pragma unroll
        for (int i = 0; i < 4; i++)
            #pragma unroll
            for (int j = 0; j < 4; j++) oacc[i][j] = 0.f;
        #pragma unroll 2
        for (int kk = 0; kk < 18; kk++) {
            int kq = kk * 8 + (lane & 3);
            uint32_t a0 = __float_as_uint(Ps[r0 * PLD + kq]);
            uint32_t a1 = __float_as_uint(Ps[(r0 + 8) * PLD + kq]);
            uint32_t a2 = __float_as_uint(Ps[r0 * PLD + kq + 4]);
            uint32_t a3 = __float_as_uint(Ps[(r0 + 8) * PLD + kq + 4]);
            #pragma unroll
            for (int ni = 0; ni < 4; ni++) {
                int n = nh * 32 + ni * 8 + (lane >> 2);
                uint32_t b0 = f2tf_bits(__float_as_uint(Vs[kq * KVLD + n]));
                uint32_t b1 = f2tf_bits(__float_as_uint(Vs[(kq + 4) * KVLD + n]));
                mma8(oacc[ni], a0, a1, a2, a3, b0, b1);
            }
        }
        #pragma unroll
        for (int ni = 0; ni < 4; ni++) {
            #pragma unroll
            for (int h = 0; h < 2; h++) {
                int row = r0 + h * 8;
                float di = dinv[row];
                int t = b * Q_ + qt * 16 + (row >> 2);
                int head = kv * G_ + (row & 3);
                int col = nh * 32 + ni * 8 + 2 * (lane & 3);
                float2 o;
                o.x = roundtf(oacc[ni][h * 2 + 0] * di);
                o.y = roundtf(oacc[ni][h * 2 + 1] * di);
                *(float2*)&attn[(size_t)t * (NQ_ * HD_) + head * HD_ + col] = o;
            }
        }
    }
}

// ---------------- fused rmsnorm2 + router ----------------
__global__ void rms_router(const float* __restrict__ in,
                           const float* __restrict__ w,
                           const float* __restrict__ wr,
                           const float* __restrict__ br,
                           float* __restrict__ x2,
                           int* __restrict__ eidx, float* __restrict__ ewt) {
    int t = blockIdx.x, tid = threadIdx.x;
    const float* x = in + (size_t)t * H_;
    __shared__ float red[256];
    __shared__ float lac[256][E_];
    float ss = 0.f;
    for (int i = tid; i < H_; i += 256) { float v = x[i]; ss += v * v; }
    red[tid] = ss; __syncthreads();
    for (int s = 128; s > 0; s >>= 1) {
        if (tid < s) red[tid] += red[tid + s];
        __syncthreads();
    }
    float r = rsqrtf(red[0] / (float)H_ + EPS_);
    float acc[E_];
    #pragma unroll
    for (int e = 0; e < E_; e++) acc[e] = 0.f;
    for (int i = tid; i < H_; i += 256) {
        float v = x[i] * w[i] * r;
        x2[(size_t)t * H_ + i] = v;
        #pragma unroll
        for (int e = 0; e < E_; e++) acc[e] += v * wr[i * E_ + e];
    }
    #pragma unroll
    for (int e = 0; e < E_; e++) lac[tid][e] = acc[e];
    __syncthreads();
    for (int s = 128; s > 0; s >>= 1) {
        if (tid < s)
            #pragma unroll
            for (int e = 0; e < E_; e++) lac[tid][e] += lac[tid + s][e];
        __syncthreads();
    }
    if (tid == 0) {
        float l[E_];
        #pragma unroll
        for (int e = 0; e < E_; e++) l[e] = lac[0][e] + br[e];
        int i0 = 0; float v0 = l[0];
        #pragma unroll
        for (int e = 1; e < E_; e++) if (l[e] > v0) { v0 = l[e]; i0 = e; }
        int i1 = -1; float v1 = -1e30f;
        #pragma unroll
        for (int e = 0; e < E_; e++)
            if (e != i0 && l[e] > v1) { v1 = l[e]; i1 = e; }
        float e1 = expf(v1 - v0);
        float inv = 1.f / (1.f + e1);
        eidx[t * 2 + 0] = i0; eidx[t * 2 + 1] = i1;
        ewt[t * 2 + 0] = inv; ewt[t * 2 + 1] = e1 * inv;
    }
}

// ---------------- route sort ----------------
__global__ void route_sort_kernel(const int* __restrict__ eidx,
                                  int* __restrict__ eoff, int* __restrict__ ecnt,
                                  int* __restrict__ tokof, int* __restrict__ slotmap) {
    __shared__ int cnt[E_];
    __shared__ int pos[E_];
    int tid = threadIdx.x;
    if (tid < E_) cnt[tid] = 0;
    for (int i = tid; i < NAPAD; i += 256) tokof[i] = -1;
    __syncthreads();
    for (int a = tid; a < T_ * 2; a += 256) atomicAdd(&cnt[eidx[a]], 1);
    __syncthreads();
    if (tid == 0) {
        int off = 0;
        for (int e = 0; e < E_; e++) {
            eoff[e] = off; ecnt[e] = cnt[e]; pos[e] = off;
            off += ((cnt[e] + 127) / 128) * 128;
        }
    }
    __syncthreads();
    for (int a = tid; a < T_ * 2; a += 256) {
        int e = eidx[a];
        int slot = atomicAdd(&pos[e], 1);
        tokof[slot] = a;
        slotmap[a] = slot;
    }
}

// ---------------- gather (rounds to tf32 for GEMM A) ----------------
__global__ void gather_kernel(const float* __restrict__ x2,
                              const int* __restrict__ tokof,
                              float* __restrict__ xg) {
    int slot = blockIdx.x;
    int a = tokof[slot];
    float4* dst = (float4*)(xg + (size_t)slot * H_);
    if (a < 0) {
        dst[threadIdx.x] = make_float4(0.f, 0.f, 0.f, 0.f);
    } else {
        float4 v = ((const float4*)(x2 + (size_t)(a >> 1) * H_))[threadIdx.x];
        v.x = roundtf(v.x); v.y = roundtf(v.y);
        v.z = roundtf(v.z); v.w = roundtf(v.w);
        dst[threadIdx.x] = v;
    }
}

// ---------------- combine ----------------
__global__ void combine_kernel(const float* __restrict__ eop,
                               const int* __restrict__ slotmap,
                               const int* __restrict__ eidx,
                               const float* __restrict__ ewt,
                               const float* __restrict__ bd,
                               float* __restrict__ out) {
    int t = blockIdx.x, i = threadIdx.x;
    float4 o = ((float4*)(out + (size_t)t * H_))[i];
    #pragma unroll
    for (int ei = 0; ei < 2; ei++) {
        int s = slotmap[t * 2 + ei];
        int e = eidx[t * 2 + ei];
        float w = ewt[t * 2 + ei];
        float4 a = ((const float4*)(eop + (size_t)s * H_))[i];
        float4 b = ((const float4*)(eop + (size_t)(NAPAD + s) * H_))[i];
        float4 c = ((const float4*)(bd + (size_t)e * H_))[i];
        o.x += w * (a.x + b.x + c.x);
        o.y += w * (a.y + b.y + c.y);
        o.z += w * (a.z + b.z + c.z);
        o.w += w * (a.w + b.w + c.w);
    }
    ((float4*)(out + (size_t)t * H_))[i] = o;
}

// ---------------- launch ----------------
extern "C" void kernel_launch(void* const* d_in, const int* in_sizes, int n_in,
                              void* d_out, int out_size) {
    const float* hidden = (const float*)d_in[0];
    const float* kvc    = (const float*)d_in[1];
    const int*   pidx   = (const int*)d_in[3];
    const float* sinks  = (const float*)d_in[4];
    const float* w_qkv  = (const float*)d_in[5];
    const float* b_qkv  = (const float*)d_in[6];
    const float* w_o    = (const float*)d_in[7];
    const float* b_o    = (const float*)d_in[8];
    const float* ln1    = (const float*)d_in[9];
    const float* ln2    = (const float*)d_in[10];
    const float* w_r    = (const float*)d_in[11];
    const float* b_r    = (const float*)d_in[12];
    const float* w_gu   = (const float*)d_in[13];
    const float* b_gu   = (const float*)d_in[14];
    const float* w_d    = (const float*)d_in[15];
    const float* b_d    = (const float*)d_in[16];
    float* out = (float*)d_out;

    float *px, *pqkvp, *pattn, *poutp, *px2, *pewt, *pxg, *pact, *peop;
    int *peidx, *peoff, *pecnt, *ptokof, *pslot;
    cudaGetSymbolAddress((void**)&px,     g_x);
    cudaGetSymbolAddress((void**)&pqkvp,  g_qkvp);
    cudaGetSymbolAddress((void**)&pattn,  g_attn);
    cudaGetSymbolAddress((void**)&poutp,  g_outp);
    cudaGetSymbolAddress((void**)&px2,    g_x2);
    cudaGetSymbolAddress((void**)&peidx,  g_eidx);
    cudaGetSymbolAddress((void**)&pewt,   g_ewt);
    cudaGetSymbolAddress((void**)&peoff,  g_eoff);
    cudaGetSymbolAddress((void**)&pecnt,  g_ecnt);
    cudaGetSymbolAddress((void**)&ptokof, g_tokof);
    cudaGetSymbolAddress((void**)&pslot,  g_slotmap);
    cudaGetSymbolAddress((void**)&pxg,    g_xg);
    cudaGetSymbolAddress((void**)&pact,   g_act);
    cudaGetSymbolAddress((void**)&peop,   g_eop);

    cudaFuncSetAttribute(attn_mma,
                         cudaFuncAttributeMaxDynamicSharedMemorySize, ATT_SMEM);
    cudaFuncSetAttribute(gemm_tf32<0, 2>,
                         cudaFuncAttributeMaxDynamicSharedMemorySize, GEMM_SMEM);
    cudaFuncSetAttribute(gemm_tf32<0, 4>,
                         cudaFuncAttributeMaxDynamicSharedMemorySize, GEMM_SMEM);
    cudaFuncSetAttribute(gemm_tf32<2, 1>,
                         cudaFuncAttributeMaxDynamicSharedMemorySize, GEMM_SMEM);
    cudaFuncSetAttribute(gemm_tf32<3, 2>,
                         cudaFuncAttributeMaxDynamicSharedMemorySize, GEMM_SMEM);

    rmsnorm_kernel<<<T_, 256>>>(hidden, ln1, px);
    gemm_tf32<0, 2><<<dim3(QKVD / 128, T_ / 128, 2), 256, GEMM_SMEM>>>(
        px, w_qkv, nullptr, pqkvp, H_, QKVD, T_ * QKVD, nullptr, nullptr);
    attn_mma<<<dim3(Q_ / 16, NKV_, B_), 256, ATT_SMEM>>>(
        pqkvp, b_qkv, kvc, pidx, sinks, pattn);
    gemm_tf32<0, 4><<<dim3(H_ / 128, T_ / 128, 4), 256, GEMM_SMEM>>>(
        pattn, w_o, nullptr, poutp, H_, H_, T_ * H_, nullptr, nullptr);
    out_reduce<<<T_, 256>>>(poutp, hidden, b_o, out);
    rms_router<<<T_, 256>>>(out, ln2, w_r, b_r, px2, peidx, pewt);
    route_sort_kernel<<<1, 256>>>(peidx, peoff, pecnt, ptokof, pslot);
    gather_kernel<<<NAPAD, 256>>>(px2, ptokof, pxg);
    gemm_tf32<2, 1><<<dim3(2 * FFN_ / 128, 8, E_), 256, GEMM_SMEM>>>(
        pxg, w_gu, b_gu, pact, H_, 2 * FFN_, 0, peoff, pecnt);
    gemm_tf32<3, 2><<<dim3(H_ / 128, 8, E_ * 2), 256, GEMM_SMEM>>>(
        pact, w_d, nullptr, peop, FFN_, H_, NAPAD * H_, peoff, pecnt);
    combine_kernel<<<T_, 256>>>(peop, pslot, peidx, pewt, b_d, out);
}